// round 7
// baseline (speedup 1.0000x reference)
#include <cuda_runtime.h>

#define N_PTS 65536
#define N_NODES 4096
#define KSEL 20
#define IN_STRIDE 35
#define CAND_CAP 24
#define NBINS 4096       // point Morton bins (16^3)
#define NCELLS 4096      // node grid cells (16^3, linear x+16y+256z)
#define GD 16
#define H 0.375f
#define INVH (1.0f / 0.375f)

__device__ float4 g_nodes4s[N_NODES];      // sorted by cell: (vx,vy,vz,|v|^2)
__device__ float4 g_rec_s[N_NODES * 4];    // sorted records: R, g+t, g
__device__ int    g_cellStart[NCELLS + 1];
__device__ int    g_cellCursor[NCELLS];
__device__ int    g_cellCount[NCELLS];
__device__ int    g_nodeCell[N_NODES];
__device__ int    g_nodePerm[N_NODES];
__device__ int    g_binCount[NBINS];
__device__ int    g_binCursor[NBINS];
__device__ int    g_cellArr[N_PTS];
__device__ int    g_perm[N_PTS];

// ---------------- point Morton binning (unchanged from R3) ----------------
__device__ __forceinline__ unsigned expand3(unsigned v) {
    return (v & 1u) | ((v & 2u) << 2) | ((v & 4u) << 4) | ((v & 8u) << 6);
}
__device__ __forceinline__ int quant4(float x) {
    int q = (int)floorf((x + 3.0f) * INVH);
    return q < 0 ? 0 : (q > 15 ? 15 : q);
}

__global__ void zero_kernel() {
    int i = blockIdx.x * blockDim.x + threadIdx.x;
    if (i < NBINS) g_binCount[i] = 0;
    if (i < NCELLS) g_cellCount[i] = 0;
}

__global__ void bin_count_kernel(const float* __restrict__ inputs) {
    int pt = blockIdx.x * blockDim.x + threadIdx.x;
    if (pt >= N_PTS) return;
    const float* pr = inputs + (long)pt * IN_STRIDE;
    unsigned code = expand3(quant4(pr[0])) | (expand3(quant4(pr[1])) << 1)
                  | (expand3(quant4(pr[2])) << 2);
    g_cellArr[pt] = (int)code;
    atomicAdd(&g_binCount[code], 1);
}

__global__ void scan_bins_kernel() {
    __shared__ int ssum[1024];
    int tid = threadIdx.x;
    int base = tid * 4;
    int c0 = g_binCount[base], c1 = g_binCount[base+1];
    int c2 = g_binCount[base+2], c3 = g_binCount[base+3];
    ssum[tid] = c0 + c1 + c2 + c3;
    __syncthreads();
    for (int off = 1; off < 1024; off <<= 1) {
        int v = ssum[tid];
        int add = (tid >= off) ? ssum[tid - off] : 0;
        __syncthreads();
        ssum[tid] = v + add;
        __syncthreads();
    }
    int excl = (tid > 0) ? ssum[tid - 1] : 0;
    g_binCursor[base]   = excl;
    g_binCursor[base+1] = excl + c0;
    g_binCursor[base+2] = excl + c0 + c1;
    g_binCursor[base+3] = excl + c0 + c1 + c2;
}

__global__ void scatter_kernel() {
    int pt = blockIdx.x * blockDim.x + threadIdx.x;
    if (pt >= N_PTS) return;
    int pos = atomicAdd(&g_binCursor[g_cellArr[pt]], 1);
    g_perm[pos] = pt;
}

// ---------------- node grid build ----------------
__global__ void node_count_kernel(const float* __restrict__ vd) {
    int j = blockIdx.x * blockDim.x + threadIdx.x;
    if (j >= N_NODES) return;
    int cx = quant4(vd[j*3+0]), cy = quant4(vd[j*3+1]), cz = quant4(vd[j*3+2]);
    int cell = cx + cy * GD + cz * GD * GD;
    g_nodeCell[j] = cell;
    atomicAdd(&g_cellCount[cell], 1);
}

__global__ void scan_cells_kernel() {
    __shared__ int ssum[1024];
    int tid = threadIdx.x;
    int base = tid * 4;
    int c0 = g_cellCount[base], c1 = g_cellCount[base+1];
    int c2 = g_cellCount[base+2], c3 = g_cellCount[base+3];
    ssum[tid] = c0 + c1 + c2 + c3;
    __syncthreads();
    for (int off = 1; off < 1024; off <<= 1) {
        int v = ssum[tid];
        int add = (tid >= off) ? ssum[tid - off] : 0;
        __syncthreads();
        ssum[tid] = v + add;
        __syncthreads();
    }
    int excl = (tid > 0) ? ssum[tid - 1] : 0;
    g_cellStart[base]    = excl;
    g_cellCursor[base]   = excl;
    g_cellStart[base+1]  = excl + c0;
    g_cellCursor[base+1] = excl + c0;
    g_cellStart[base+2]  = excl + c0 + c1;
    g_cellCursor[base+2] = excl + c0 + c1;
    g_cellStart[base+3]  = excl + c0 + c1 + c2;
    g_cellCursor[base+3] = excl + c0 + c1 + c2;
    if (tid == 1023) g_cellStart[NCELLS] = N_NODES;
}

__global__ void node_scatter_kernel() {
    int j = blockIdx.x * blockDim.x + threadIdx.x;
    if (j >= N_NODES) return;
    int pos = atomicAdd(&g_cellCursor[g_nodeCell[j]], 1);
    g_nodePerm[pos] = j;
}

__global__ void build_sorted_kernel(const float* __restrict__ vd, const float* __restrict__ R,
                                    const float* __restrict__ g, const float* __restrict__ t) {
    int pos = blockIdx.x * blockDim.x + threadIdx.x;
    if (pos >= N_NODES) return;
    int j = g_nodePerm[pos];
    float vx = vd[j*3+0], vy = vd[j*3+1], vz = vd[j*3+2];
    g_nodes4s[pos] = make_float4(vx, vy, vz, fmaf(vx,vx,fmaf(vy,vy,vz*vz)));
    const float* Rj = R + j*9;
    float g0 = g[j*3+0], g1 = g[j*3+1], g2 = g[j*3+2];
    float gt0 = g0 + t[j*3+0], gt1 = g1 + t[j*3+1], gt2 = g2 + t[j*3+2];
    g_rec_s[pos*4+0] = make_float4(Rj[0], Rj[1], Rj[2], Rj[3]);
    g_rec_s[pos*4+1] = make_float4(Rj[4], Rj[5], Rj[6], Rj[7]);
    g_rec_s[pos*4+2] = make_float4(Rj[8], gt0, gt1, gt2);
    g_rec_s[pos*4+3] = make_float4(g0, g1, g2, 0.0f);
}

// ---------------- main kernel ----------------
#define SCAN_CELL(CIDX) do {                                                   \
    int _c = (CIDX);                                                           \
    int _s0 = g_cellStart[_c], _s1 = g_cellStart[_c + 1];                      \
    for (int _n = _s0; _n < _s1; _n++) {                                       \
        float4 _v = __ldg(&g_nodes4s[_n]);                                     \
        float _s = fmaf(qa, _v.x, fmaf(qb, _v.y, fmaf(qc, _v.z, _v.w)));       \
        if (__any_sync(0xffffffffu, _s < d[KSEL-1])) {                         \
            _Pragma("unroll")                                                  \
            for (int _k = KSEL-1; _k >= 1; --_k)                               \
                d[_k] = fminf(d[_k], fmaxf(d[_k-1], _s));                      \
            d[0] = fminf(d[0], _s);                                            \
        }                                                                      \
    }                                                                          \
} while (0)

__global__ void __launch_bounds__(128) dg_kernel(const float* __restrict__ inputs,
                                                 float* __restrict__ out) {
    const int tid = threadIdx.x;
    const int pt = g_perm[blockIdx.x * 128 + tid];
    const float* pr = inputs + (long)pt * IN_STRIDE;
    const float px = pr[0], py = pr[1], pz = pr[2];
    const float pp = fmaf(px, px, fmaf(py, py, pz * pz));
    const float qa = -2.0f * px, qb = -2.0f * py, qc = -2.0f * pz;

    const int cx = quant4(px), cy = quant4(py), cz = quant4(pz);

    // warp cell-box via shuffle reduces
    int lx = cx, hx = cx, ly = cy, hy = cy, lz = cz, hz = cz;
    #pragma unroll
    for (int o = 16; o; o >>= 1) {
        lx = min(lx, __shfl_xor_sync(0xffffffffu, lx, o));
        hx = max(hx, __shfl_xor_sync(0xffffffffu, hx, o));
        ly = min(ly, __shfl_xor_sync(0xffffffffu, ly, o));
        hy = max(hy, __shfl_xor_sync(0xffffffffu, hy, o));
        lz = min(lz, __shfl_xor_sync(0xffffffffu, lz, o));
        hz = max(hz, __shfl_xor_sync(0xffffffffu, hz, o));
    }
    const int rho_cover = max(max(max(lx, GD-1-hx), max(ly, GD-1-hy)),
                              max(lz, GD-1-hz));

    float d[KSEL];
    #pragma unroll
    for (int k = 0; k < KSEL; k++) d[k] = 3.0e38f;

    // ---- Pass 1: expanding Chebyshev rings around the warp box ----
    int rho = 0;
    while (true) {
        int zl = max(lz - rho, 0), zh = min(hz + rho, GD-1);
        for (int z = zl; z <= zh; z++) {
            int dz = max(max(lz - z, z - hz), 0);
            int yl = max(ly - rho, 0), yh = min(hy + rho, GD-1);
            int zb = z * GD * GD;
            for (int y = yl; y <= yh; y++) {
                int dy = max(max(ly - y, y - hy), 0);
                int base = zb + y * GD;
                if (dz == rho || dy == rho) {
                    int xl = max(lx - rho, 0), xh = min(hx + rho, GD-1);
                    for (int x = xl; x <= xh; x++) SCAN_CELL(base + x);
                } else {
                    int x1 = lx - rho, x2 = hx + rho;
                    if (x1 >= 0) SCAN_CELL(base + x1);
                    if (x2 <= GD-1 && x2 != x1) SCAN_CELL(base + x2);
                }
            }
        }
        float rb = (float)rho * H;
        bool need = (d[KSEL-1] + pp) > rb * rb;
        if (!__any_sync(0xffffffffu, need)) break;
        if (rho >= rho_cover) break;
        rho++;
    }

    const float T = d[KSEL-1];
    const float dis0 = d[0] + pp;
    const float dismax = T + pp;
    const float rcpmax = 1.0f / dismax;

    // ---- Pass 2: collect ids with s <= T over the final box ----
    int   ids[CAND_CAP];
    float ssv[CAND_CAP];
    int cnt = 0;
    {
        int zl = max(lz - rho, 0), zh = min(hz + rho, GD-1);
        int yl = max(ly - rho, 0), yh = min(hy + rho, GD-1);
        int xl = max(lx - rho, 0), xh = min(hx + rho, GD-1);
        for (int z = zl; z <= zh; z++) {
            int zb = z * GD * GD;
            for (int y = yl; y <= yh; y++) {
                int base = zb + y * GD;
                int s0 = g_cellStart[base + xl];
                int s1 = g_cellStart[base + xh + 1];   // contiguous x-run of cells
                for (int n = s0; n < s1; n++) {
                    float4 v = __ldg(&g_nodes4s[n]);
                    float s = fmaf(qa, v.x, fmaf(qb, v.y, fmaf(qc, v.z, v.w)));
                    if (s <= T && cnt < CAND_CAP) {
                        ids[cnt] = n;
                        ssv[cnt] = s;
                        cnt++;
                    }
                }
            }
        }
    }

    // ---- Phase 3: gather sorted node records, weight, blend ----
    float wsum = 0.0f, pb0 = 0.0f, pb1 = 0.0f, pb2 = 0.0f;
    float rb9[9];
    #pragma unroll
    for (int i = 0; i < 9; i++) rb9[i] = 0.0f;

    for (int k = 0; k < cnt; k++) {
        int n = ids[k];
        float dis = ssv[k] + pp;
        float u = 1.0f - dis * rcpmax;
        float w = u * u;
        const float4* rec = g_rec_s + n * 4;
        float4 r0 = __ldg(rec + 0);
        float4 r1 = __ldg(rec + 1);
        float4 r2v = __ldg(rec + 2);
        float4 r3 = __ldg(rec + 3);
        float y0 = px - r2v.y, y1 = py - r2v.z, y2 = pz - r2v.w;
        float q0 = fmaf(r0.x, y0, fmaf(r0.w, y1, fmaf(r1.z, y2, r3.x)));
        float q1 = fmaf(r0.y, y0, fmaf(r1.x, y1, fmaf(r1.w, y2, r3.y)));
        float q2 = fmaf(r0.z, y0, fmaf(r1.y, y1, fmaf(r2v.x, y2, r3.z)));
        wsum += w;
        pb0 = fmaf(w, q0, pb0);
        pb1 = fmaf(w, q1, pb1);
        pb2 = fmaf(w, q2, pb2);
        rb9[0] = fmaf(w, r0.x, rb9[0]);
        rb9[1] = fmaf(w, r0.w, rb9[1]);
        rb9[2] = fmaf(w, r1.z, rb9[2]);
        rb9[3] = fmaf(w, r0.y, rb9[3]);
        rb9[4] = fmaf(w, r1.x, rb9[4]);
        rb9[5] = fmaf(w, r1.w, rb9[5]);
        rb9[6] = fmaf(w, r0.z, rb9[6]);
        rb9[7] = fmaf(w, r1.y, rb9[7]);
        rb9[8] = fmaf(w, r2v.x, rb9[8]);
    }

    const float inv = 1.0f / wsum;
    float o0 = (dis0 > 0.00021f) ? 1000000000.0f : pb0 * inv;
    float* op = out + (long)pt * 3;
    op[0] = o0;
    op[1] = pb1 * inv;
    op[2] = pb2 * inv;
    float* orr = out + (long)N_PTS * 3 + (long)pt * 9;
    #pragma unroll
    for (int i = 0; i < 9; i++) orr[i] = rb9[i] * inv;
}

extern "C" void kernel_launch(void* const* d_in, const int* in_sizes, int n_in,
                              void* d_out, int out_size) {
    const float* inputs = (const float*)d_in[0];
    const float* vd     = (const float*)d_in[1];
    const float* R      = (const float*)d_in[2];
    const float* g      = (const float*)d_in[3];
    const float* t      = (const float*)d_in[4];
    float* out = (float*)d_out;

    zero_kernel<<<NBINS / 256, 256>>>();
    bin_count_kernel<<<N_PTS / 256, 256>>>(inputs);
    node_count_kernel<<<N_NODES / 256, 256>>>(vd);
    scan_bins_kernel<<<1, 1024>>>();
    scan_cells_kernel<<<1, 1024>>>();
    scatter_kernel<<<N_PTS / 256, 256>>>();
    node_scatter_kernel<<<N_NODES / 256, 256>>>();
    build_sorted_kernel<<<N_NODES / 256, 256>>>(vd, R, g, t);
    dg_kernel<<<N_PTS / 128, 128>>>(inputs, out);
}

// round 8
// speedup vs baseline: 2.3823x; 2.3823x over previous
#include <cuda_runtime.h>

#define N_PTS 65536
#define N_NODES 4096
#define KSEL 20
#define IN_STRIDE 35
#define NBINS 4096
#define NGROUPS 512
#define GSZ 8

__device__ float4 g_nodes4s[N_NODES];     // Morton-sorted: (vx,vy,vz,|v|^2)
__device__ float4 g_rec_s[N_NODES * 4];   // sorted records: R, g+t, g
__device__ float4 g_group[NGROUPS];       // (cx,cy,cz, r+margin)
__device__ int g_binCount[NBINS], g_binCursor[NBINS], g_cellArr[N_PTS], g_perm[N_PTS];
__device__ int g_nBinCount[NBINS], g_nBinCursor[NBINS], g_nCell[N_NODES], g_nPerm[N_NODES];

__device__ __forceinline__ unsigned expand3(unsigned v) {
    return (v & 1u) | ((v & 2u) << 2) | ((v & 4u) << 4) | ((v & 8u) << 6);
}
__device__ __forceinline__ int quant4(float x) {
    int q = (int)floorf((x + 3.0f) * (16.0f / 6.0f));
    return q < 0 ? 0 : (q > 15 ? 15 : q);
}
__device__ __forceinline__ unsigned morton3(float x, float y, float z) {
    return expand3(quant4(x)) | (expand3(quant4(y)) << 1) | (expand3(quant4(z)) << 2);
}

__global__ void zero_kernel() {
    int i = blockIdx.x * blockDim.x + threadIdx.x;
    if (i < NBINS) { g_binCount[i] = 0; g_nBinCount[i] = 0; }
}

__global__ void bin_count_kernel(const float* __restrict__ inputs) {
    int pt = blockIdx.x * blockDim.x + threadIdx.x;
    if (pt >= N_PTS) return;
    const float* pr = inputs + (long)pt * IN_STRIDE;
    unsigned code = morton3(pr[0], pr[1], pr[2]);
    g_cellArr[pt] = (int)code;
    atomicAdd(&g_binCount[code], 1);
}

__global__ void node_count_kernel(const float* __restrict__ vd) {
    int j = blockIdx.x * blockDim.x + threadIdx.x;
    if (j >= N_NODES) return;
    unsigned code = morton3(vd[j*3+0], vd[j*3+1], vd[j*3+2]);
    g_nCell[j] = (int)code;
    atomicAdd(&g_nBinCount[code], 1);
}

__global__ void scan_points_kernel() {
    __shared__ int ssum[1024];
    int tid = threadIdx.x;
    int base = tid * 4;
    int c0 = g_binCount[base], c1 = g_binCount[base+1];
    int c2 = g_binCount[base+2], c3 = g_binCount[base+3];
    ssum[tid] = c0 + c1 + c2 + c3;
    __syncthreads();
    for (int off = 1; off < 1024; off <<= 1) {
        int v = ssum[tid];
        int add = (tid >= off) ? ssum[tid - off] : 0;
        __syncthreads();
        ssum[tid] = v + add;
        __syncthreads();
    }
    int excl = (tid > 0) ? ssum[tid - 1] : 0;
    g_binCursor[base]   = excl;
    g_binCursor[base+1] = excl + c0;
    g_binCursor[base+2] = excl + c0 + c1;
    g_binCursor[base+3] = excl + c0 + c1 + c2;
}

__global__ void scan_nodes_kernel() {
    __shared__ int ssum[1024];
    int tid = threadIdx.x;
    int base = tid * 4;
    int c0 = g_nBinCount[base], c1 = g_nBinCount[base+1];
    int c2 = g_nBinCount[base+2], c3 = g_nBinCount[base+3];
    ssum[tid] = c0 + c1 + c2 + c3;
    __syncthreads();
    for (int off = 1; off < 1024; off <<= 1) {
        int v = ssum[tid];
        int add = (tid >= off) ? ssum[tid - off] : 0;
        __syncthreads();
        ssum[tid] = v + add;
        __syncthreads();
    }
    int excl = (tid > 0) ? ssum[tid - 1] : 0;
    g_nBinCursor[base]   = excl;
    g_nBinCursor[base+1] = excl + c0;
    g_nBinCursor[base+2] = excl + c0 + c1;
    g_nBinCursor[base+3] = excl + c0 + c1 + c2;
}

__global__ void scatter_points_kernel() {
    int pt = blockIdx.x * blockDim.x + threadIdx.x;
    if (pt >= N_PTS) return;
    int pos = atomicAdd(&g_binCursor[g_cellArr[pt]], 1);
    g_perm[pos] = pt;
}

__global__ void scatter_nodes_kernel() {
    int j = blockIdx.x * blockDim.x + threadIdx.x;
    if (j >= N_NODES) return;
    int pos = atomicAdd(&g_nBinCursor[g_nCell[j]], 1);
    g_nPerm[pos] = j;
}

__global__ void build_sorted_kernel(const float* __restrict__ vd, const float* __restrict__ R,
                                    const float* __restrict__ g, const float* __restrict__ t) {
    int pos = blockIdx.x * blockDim.x + threadIdx.x;
    if (pos >= N_NODES) return;
    int j = g_nPerm[pos];
    float vx = vd[j*3+0], vy = vd[j*3+1], vz = vd[j*3+2];
    g_nodes4s[pos] = make_float4(vx, vy, vz, fmaf(vx,vx,fmaf(vy,vy,vz*vz)));
    const float* Rj = R + j*9;
    float g0 = g[j*3+0], g1 = g[j*3+1], g2 = g[j*3+2];
    float gt0 = g0 + t[j*3+0], gt1 = g1 + t[j*3+1], gt2 = g2 + t[j*3+2];
    g_rec_s[pos*4+0] = make_float4(Rj[0], Rj[1], Rj[2], Rj[3]);
    g_rec_s[pos*4+1] = make_float4(Rj[4], Rj[5], Rj[6], Rj[7]);
    g_rec_s[pos*4+2] = make_float4(Rj[8], gt0, gt1, gt2);
    g_rec_s[pos*4+3] = make_float4(g0, g1, g2, 0.0f);
}

__global__ void group_build_kernel() {
    int gi = blockIdx.x * blockDim.x + threadIdx.x;
    if (gi >= NGROUPS) return;
    float cx = 0.0f, cy = 0.0f, cz = 0.0f;
    float4 nb[GSZ];
    #pragma unroll
    for (int u = 0; u < GSZ; u++) {
        nb[u] = g_nodes4s[gi * GSZ + u];
        cx += nb[u].x; cy += nb[u].y; cz += nb[u].z;
    }
    cx *= (1.0f / GSZ); cy *= (1.0f / GSZ); cz *= (1.0f / GSZ);
    float r2 = 0.0f;
    #pragma unroll
    for (int u = 0; u < GSZ; u++) {
        float dx = nb[u].x - cx, dy = nb[u].y - cy, dz = nb[u].z - cz;
        r2 = fmaxf(r2, fmaf(dx, dx, fmaf(dy, dy, dz * dz)));
    }
    g_group[gi] = make_float4(cx, cy, cz, sqrtf(r2) + 1e-3f);
}

#define INSERT_S(SV) do {                                              \
    _Pragma("unroll")                                                  \
    for (int _k = KSEL-1; _k >= 1; --_k)                               \
        d[_k] = fminf(d[_k], fmaxf(d[_k-1], (SV)));                    \
    d[0] = fminf(d[0], (SV));                                          \
} while (0)

__global__ void __launch_bounds__(128) dg_kernel(const float* __restrict__ inputs,
                                                 float* __restrict__ out) {
    __shared__ float4 sg[NGROUPS];   // 8 KB
    const int tid  = threadIdx.x;
    const int lane = tid & 31;

    for (int i = tid; i < NGROUPS; i += 128) sg[i] = g_group[i];
    __syncthreads();

    const int pt = g_perm[blockIdx.x * 128 + tid];
    const float* pr = inputs + (long)pt * IN_STRIDE;
    const float px = pr[0], py = pr[1], pz = pr[2];
    const float pp = fmaf(px, px, fmaf(py, py, pz * pz));
    const float qa = -2.0f * px, qb = -2.0f * py, qc = -2.0f * pz;

    // ---- warp centroid ----
    float wx = px, wy = py, wz = pz;
    #pragma unroll
    for (int o = 16; o; o >>= 1) {
        wx += __shfl_xor_sync(0xffffffffu, wx, o);
        wy += __shfl_xor_sync(0xffffffffu, wy, o);
        wz += __shfl_xor_sync(0xffffffffu, wz, o);
    }
    wx *= (1.0f/32.0f); wy *= (1.0f/32.0f); wz *= (1.0f/32.0f);

    // ---- warp-uniform argmin group (tie-broken by index) ----
    float bestd = 3.0e38f; int bestg = 0;
    for (int i = lane; i < NGROUPS; i += 32) {
        float4 gc = sg[i];
        float dx = gc.x - wx, dy = gc.y - wy, dz = gc.z - wz;
        float d2 = fmaf(dx, dx, fmaf(dy, dy, dz * dz));
        if (d2 < bestd) { bestd = d2; bestg = i; }
    }
    #pragma unroll
    for (int o = 16; o; o >>= 1) {
        float od = __shfl_xor_sync(0xffffffffu, bestd, o);
        int   og = __shfl_xor_sync(0xffffffffu, bestg, o);
        if (od < bestd || (od == bestd && og < bestg)) { bestd = od; bestg = og; }
    }

    int seedLo = bestg - 3;
    if (seedLo < 0) seedLo = 0;
    if (seedLo > NGROUPS - 8) seedLo = NGROUPS - 8;
    const int seedHi = seedLo + 8;

    // ---- seed: unconditional scan of 8 Morton-local groups ----
    float d[KSEL];
    #pragma unroll
    for (int k = 0; k < KSEL; k++) d[k] = 3.0e38f;

    for (int n = seedLo * GSZ; n < seedHi * GSZ; n++) {
        float4 v = __ldg(&g_nodes4s[n]);
        float s = fmaf(qa, v.x, fmaf(qb, v.y, fmaf(qc, v.z, v.w)));
        if (__any_sync(0xffffffffu, s < d[KSEL-1])) INSERT_S(s);
    }

    float sd = sqrtf(fmaxf(d[KSEL-1] + pp, 0.0f));

    // ---- Pass 1: flat sweep over 512 groups with sphere test ----
    for (int gi = 0; gi < NGROUPS; gi++) {
        if (gi == seedLo) { gi = seedHi - 1; continue; }   // skip seed (no dup inserts)
        float4 gc = sg[gi];
        float dx = gc.x - px, dy = gc.y - py, dz = gc.z - pz;
        float d2 = fmaf(dx, dx, fmaf(dy, dy, dz * dz));
        float tt = sd + gc.w;
        if (__any_sync(0xffffffffu, d2 < tt * tt)) {
            bool fired = false;
            #pragma unroll
            for (int u = 0; u < GSZ; u++) {
                float4 v = __ldg(&g_nodes4s[gi * GSZ + u]);
                float s = fmaf(qa, v.x, fmaf(qb, v.y, fmaf(qc, v.z, v.w)));
                if (__any_sync(0xffffffffu, s < d[KSEL-1])) { INSERT_S(s); fired = true; }
            }
            if (fired) sd = sqrtf(fmaxf(d[KSEL-1] + pp, 0.0f));
        }
    }

    const float T = d[KSEL-1];
    const float dis0 = d[0] + pp;
    const float dismax = T + pp;
    const float rcpmax = 1.0f / dismax;
    const float sdT = sqrtf(fmaxf(dismax, 0.0f)) + 1e-4f;

    // ---- Pass 2 (fused blend): sweep groups, blend nodes with s <= T ----
    float wsum = 0.0f, pb0 = 0.0f, pb1 = 0.0f, pb2 = 0.0f;
    float rb9[9];
    #pragma unroll
    for (int i = 0; i < 9; i++) rb9[i] = 0.0f;

    for (int gi = 0; gi < NGROUPS; gi++) {
        float4 gc = sg[gi];
        float dx = gc.x - px, dy = gc.y - py, dz = gc.z - pz;
        float d2 = fmaf(dx, dx, fmaf(dy, dy, dz * dz));
        float tt = sdT + gc.w;
        if (__any_sync(0xffffffffu, d2 < tt * tt)) {
            #pragma unroll
            for (int u = 0; u < GSZ; u++) {
                int n = gi * GSZ + u;
                float4 v = __ldg(&g_nodes4s[n]);
                float s = fmaf(qa, v.x, fmaf(qb, v.y, fmaf(qc, v.z, v.w)));
                if (__any_sync(0xffffffffu, s <= T)) {
                    if (s <= T) {
                        float dis = s + pp;
                        float uu = 1.0f - dis * rcpmax;
                        float w = uu * uu;
                        const float4* rec = g_rec_s + n * 4;
                        float4 r0 = __ldg(rec + 0);
                        float4 r1 = __ldg(rec + 1);
                        float4 r2v = __ldg(rec + 2);
                        float4 r3 = __ldg(rec + 3);
                        float y0 = px - r2v.y, y1 = py - r2v.z, y2 = pz - r2v.w;
                        float q0 = fmaf(r0.x, y0, fmaf(r0.w, y1, fmaf(r1.z, y2, r3.x)));
                        float q1 = fmaf(r0.y, y0, fmaf(r1.x, y1, fmaf(r1.w, y2, r3.y)));
                        float q2 = fmaf(r0.z, y0, fmaf(r1.y, y1, fmaf(r2v.x, y2, r3.z)));
                        wsum += w;
                        pb0 = fmaf(w, q0, pb0);
                        pb1 = fmaf(w, q1, pb1);
                        pb2 = fmaf(w, q2, pb2);
                        rb9[0] = fmaf(w, r0.x, rb9[0]);
                        rb9[1] = fmaf(w, r0.w, rb9[1]);
                        rb9[2] = fmaf(w, r1.z, rb9[2]);
                        rb9[3] = fmaf(w, r0.y, rb9[3]);
                        rb9[4] = fmaf(w, r1.x, rb9[4]);
                        rb9[5] = fmaf(w, r1.w, rb9[5]);
                        rb9[6] = fmaf(w, r0.z, rb9[6]);
                        rb9[7] = fmaf(w, r1.y, rb9[7]);
                        rb9[8] = fmaf(w, r2v.x, rb9[8]);
                    }
                }
            }
        }
    }

    const float inv = 1.0f / wsum;
    float o0 = (dis0 > 0.00021f) ? 1000000000.0f : pb0 * inv;
    float* op = out + (long)pt * 3;
    op[0] = o0;
    op[1] = pb1 * inv;
    op[2] = pb2 * inv;
    float* orr = out + (long)N_PTS * 3 + (long)pt * 9;
    #pragma unroll
    for (int i = 0; i < 9; i++) orr[i] = rb9[i] * inv;
}

extern "C" void kernel_launch(void* const* d_in, const int* in_sizes, int n_in,
                              void* d_out, int out_size) {
    const float* inputs = (const float*)d_in[0];
    const float* vd     = (const float*)d_in[1];
    const float* R      = (const float*)d_in[2];
    const float* g      = (const float*)d_in[3];
    const float* t      = (const float*)d_in[4];
    float* out = (float*)d_out;

    zero_kernel<<<NBINS / 256, 256>>>();
    bin_count_kernel<<<N_PTS / 256, 256>>>(inputs);
    node_count_kernel<<<N_NODES / 256, 256>>>(vd);
    scan_points_kernel<<<1, 1024>>>();
    scan_nodes_kernel<<<1, 1024>>>();
    scatter_points_kernel<<<N_PTS / 256, 256>>>();
    scatter_nodes_kernel<<<N_NODES / 256, 256>>>();
    build_sorted_kernel<<<N_NODES / 256, 256>>>(vd, R, g, t);
    group_build_kernel<<<NGROUPS / 256, 256>>>();
    dg_kernel<<<N_PTS / 128, 128>>>(inputs, out);
}